// round 6
// baseline (speedup 1.0000x reference)
#include <cuda_runtime.h>
#include <math.h>

// Problem dims
#define NXD 32
#define NYD 32
#define NZD 32
#define NBD 16
#define LMEMD 64
#define MIDD 128
#define NSAMP (NXD*NYD*NZD*NBD)   // 524288

// Tiling
#define TPB 128                 // one thread per hidden unit
#define SAMP_PER_GROUP 16
#define SAMP_PER_BLOCK 256
#define GROUPS_PER_BLOCK (SAMP_PER_BLOCK / SAMP_PER_GROUP)   // 16
#define GRID_MLP (NSAMP / SAMP_PER_BLOCK)                    // 2048

// Shared layout (float offsets)
#define OFF_W1T   0                      // 64*128   = 8192
#define OFF_W2T   8192                   // 128*128  = 16384
#define OFF_XW    24576                  // 64*16    = 1024
#define OFF_H     25600                  // 128*16   = 2048
#define OFF_ARP   27648                  // 16*8     = 128
#define OFF_W3    27776                  // 128
#define SMEM_FLOATS 27904
#define SMEM_BYTES (SMEM_FLOATS * 4)     // 111,616 B  (2 blocks/SM fits 228KB)

typedef unsigned long long ull;

// Scratch (allocation-free rule: device globals)
__device__ float g_os[NSAMP];
__device__ float g_nn[NSAMP];

__device__ __forceinline__ ull pack2(float lo, float hi) {
    ull r;
    asm("mov.b64 %0, {%1, %2};" : "=l"(r) : "f"(lo), "f"(hi));
    return r;
}
__device__ __forceinline__ void unpack2(ull v, float& lo, float& hi) {
    asm("mov.b64 {%0, %1}, %2;" : "=f"(lo), "=f"(hi) : "l"(v));
}
// d = a * b + d  (packed 2x fp32, sm_100+)
__device__ __forceinline__ void fma2(ull& d, ull a, ull b) {
    asm("fma.rn.f32x2 %0, %1, %2, %3;" : "=l"(d) : "l"(a), "l"(b), "l"(d));
}
// Accurate fast tanh: tanh(x) = 1 - 2/(e^{2x}+1), via MUFU ex2 + rcp.
// ~1e-7 error; saturates correctly (e^{2x}->inf => 1, ->0 => -1).
__device__ __forceinline__ float tanh_fast(float x) {
    float e, r;
    const float t = x * 2.885390082f;           // 2 * log2(e)
    asm("ex2.approx.f32 %0, %1;" : "=f"(e) : "f"(t));   // e = 2^(2x*log2e) = e^{2x}
    asm("rcp.approx.f32 %0, %1;" : "=f"(r) : "f"(e + 1.0f));
    return fmaf(-2.0f, r, 1.0f);
}

template <bool WITH_AR>
__global__ __launch_bounds__(TPB)
void mlp_kernel(const float* __restrict__ x,
                const float* __restrict__ weight,
                const float* __restrict__ W1, const float* __restrict__ b1,
                const float* __restrict__ W2, const float* __restrict__ b2,
                const float* __restrict__ W3, const float* __restrict__ b3,
                const float* __restrict__ ag,
                const float* __restrict__ max_os_l,
                float* __restrict__ out)
{
    extern __shared__ float smem[];
    float* sW1T = smem + OFF_W1T;   // [l][m]  l<64,  m<128
    float* sW2T = smem + OFF_W2T;   // [k][n]  k<128, n<128
    float* sXw  = smem + OFF_XW;    // [l][s]  l<64,  s<16
    float* sH   = smem + OFF_H;     // [m][s]  m<128, s<16
    float* sArp = smem + OFF_ARP;   // [s][h]  s<16,  h<8
    float* sW3  = smem + OFF_W3;    // [m]

    const int tid = threadIdx.x;
    const int m   = tid;            // hidden unit owned by this thread
    // Loader roles: lane-group spans SAMPLES (bank-friendly STS into [l][s]).
    const int s_ld = tid & 15;      // 0..15 : sample slot
    const int h_ld = tid >> 4;      // 0..7  : 8-float feature chunk

    // Block-invariant per-thread registers
    const float bb1 = b1[m];
    const float bb2 = b2[m];
    const float bb3 = b3[0];
    const float max_os = expf(max_os_l[0]);

    float wreg[8];
    float agreg[8];
#pragma unroll
    for (int k = 0; k < 8; ++k) {
        wreg[k] = weight[h_ld * 8 + k];
        agreg[k] = WITH_AR ? ag[h_ld * 8 + k] : 0.0f;
    }

    // Stage weights (transposed) into shared
    for (int i = tid; i < LMEMD * MIDD; i += TPB) {
        const int l = i >> 7, mm = i & 127;
        sW1T[i] = W1[mm * LMEMD + l];
    }
    for (int i = tid; i < MIDD * MIDD; i += TPB) {
        const int k = i >> 7, n = i & 127;
        sW2T[i] = W2[n * MIDD + k];
    }
    sW3[tid] = W3[tid];
    __syncthreads();

    const int base = blockIdx.x * SAMP_PER_BLOCK;
    const float* xrow = x + (size_t)(base + s_ld) * LMEMD + h_ld * 8;

    // ---- Prefetch group 0's x into registers ----
    float4 pv0, pv1;
    {
        const float4* xp = reinterpret_cast<const float4*>(xrow);
        pv0 = xp[0];
        pv1 = xp[1];
    }

    for (int g = 0; g < GROUPS_PER_BLOCK; ++g) {
        // ---- A: consume prefetched x, build x_w (and AR partials) ----
        // STS addr = (8*h+k)*16 + s -> bank (16k+s)%32: 16 distinct s per
        // warp => only the two h-groups collide (2-way).
        {
            float xv[8] = { pv0.x, pv0.y, pv0.z, pv0.w,
                            pv1.x, pv1.y, pv1.z, pv1.w };
            float arl = 0.0f;
#pragma unroll
            for (int k = 0; k < 8; ++k) {
                sXw[(h_ld * 8 + k) * SAMP_PER_GROUP + s_ld] = xv[k] * wreg[k];
                if (WITH_AR) arl = fmaf(xv[k], agreg[k], arl);
            }
            if (WITH_AR) sArp[s_ld * 8 + h_ld] = arl;
        }
        // ---- Prefetch group g+1's x: LDG issued here, consumed after the
        // full B..E compute span (~6k cycles) -> DRAM latency fully hidden.
        if (g + 1 < GROUPS_PER_BLOCK) {
            const float4* xp = reinterpret_cast<const float4*>(
                xrow + (size_t)(g + 1) * SAMP_PER_GROUP * LMEMD);
            pv0 = xp[0];
            pv1 = xp[1];
        }
        __syncthreads();   // S1: sXw ready

        // ---- B: layer 1 (64 -> 128), packed f32x2 over sample pairs ----
        ull acc[8];
        {
            const ull binit = pack2(bb1, bb1);
#pragma unroll
            for (int p = 0; p < 8; ++p) acc[p] = binit;
        }
#pragma unroll 8
        for (int l = 0; l < LMEMD; ++l) {
            const float w = sW1T[(l << 7) + m];
            const ull w2 = pack2(w, w);
            const ulonglong2* xr =
                reinterpret_cast<const ulonglong2*>(&sXw[l << 4]);
            const ulonglong2 q0 = xr[0], q1 = xr[1], q2 = xr[2], q3 = xr[3];
            fma2(acc[0], w2, q0.x); fma2(acc[1], w2, q0.y);
            fma2(acc[2], w2, q1.x); fma2(acc[3], w2, q1.y);
            fma2(acc[4], w2, q2.x); fma2(acc[5], w2, q2.y);
            fma2(acc[6], w2, q3.x); fma2(acc[7], w2, q3.y);
        }
#pragma unroll
        for (int p = 0; p < 8; ++p) {
            float lo, hi;
            unpack2(acc[p], lo, hi);
            *reinterpret_cast<float2*>(&sH[(m << 4) + (p << 1)]) =
                make_float2(tanh_fast(lo), tanh_fast(hi));
        }
        __syncthreads();   // S2: h1 ready

        // ---- C: layer 2 (128 -> 128), packed f32x2 ----
        {
            const ull binit = pack2(bb2, bb2);
#pragma unroll
            for (int p = 0; p < 8; ++p) acc[p] = binit;
        }
#pragma unroll 8
        for (int k = 0; k < MIDD; ++k) {
            const float w = sW2T[(k << 7) + m];
            const ull w2 = pack2(w, w);
            const ulonglong2* hr =
                reinterpret_cast<const ulonglong2*>(&sH[k << 4]);
            const ulonglong2 q0 = hr[0], q1 = hr[1], q2 = hr[2], q3 = hr[3];
            fma2(acc[0], w2, q0.x); fma2(acc[1], w2, q0.y);
            fma2(acc[2], w2, q1.x); fma2(acc[3], w2, q1.y);
            fma2(acc[4], w2, q2.x); fma2(acc[5], w2, q2.y);
            fma2(acc[6], w2, q3.x); fma2(acc[7], w2, q3.y);
        }
        __syncthreads();   // S3: all reads of sH (layer2) done

        // ---- D: write tanh(h2) into sH ----
#pragma unroll
        for (int p = 0; p < 8; ++p) {
            float lo, hi;
            unpack2(acc[p], lo, hi);
            *reinterpret_cast<float2*>(&sH[(m << 4) + (p << 1)]) =
                make_float2(tanh_fast(lo), tanh_fast(hi));
        }
        __syncthreads();   // S4: h2 ready

        // ---- E: layer 3 reduce + AR, 16 threads (one per sample) ----
        // Reads sH[(mm<<4)+tid]: 16 active lanes hit 16 consecutive banks
        // per mm -> conflict-free. 4 accumulators break the lat-4 chain.
        if (tid < SAMP_PER_GROUP) {
            float a0 = 0.0f, a1 = 0.0f, a2 = 0.0f, a3 = 0.0f;
#pragma unroll 8
            for (int mm = 0; mm < MIDD; mm += 4) {
                a0 = fmaf(sW3[mm + 0], sH[((mm + 0) << 4) + tid], a0);
                a1 = fmaf(sW3[mm + 1], sH[((mm + 1) << 4) + tid], a1);
                a2 = fmaf(sW3[mm + 2], sH[((mm + 2) << 4) + tid], a2);
                a3 = fmaf(sW3[mm + 3], sH[((mm + 3) << 4) + tid], a3);
            }
            float val = tanh_fast((a0 + a1) + (a2 + a3) + bb3) * max_os;
            if (WITH_AR) {
                float ar = 0.0f;
#pragma unroll
                for (int j = 0; j < 8; ++j) ar += sArp[tid * 8 + j];
                val += ar;
            }
            out[base + g * SAMP_PER_GROUP + tid] = val;
        }
        __syncthreads();   // S5: protect sH/sXw/sArp before next group
    }
}

// 8-point periodic stencil on g_nn + combine + sigma.
// Vectorized: each thread handles 4 contiguous ib entries (float4).
__global__ void stencil_kernel(const float* __restrict__ sigma_l,
                               float* __restrict__ out)
{
    const int t = blockIdx.x * blockDim.x + threadIdx.x;   // 0 .. NSAMP/4-1
    if (t >= NSAMP / 4) return;
    const int idx = t * 4;                 // base element index
    const int ibq = (idx & 15) >> 2;       // which float4 within the 16-bank
    const int iz = (idx >> 4) & 31;
    const int iy = (idx >> 9) & 31;
    const int ix = (idx >> 14) & 31;
    const int xm = (ix + 31) & 31, xp = (ix + 1) & 31;
    const int ym = (iy + 31) & 31, yp = (iy + 1) & 31;
    const int zm = (iz + 31) & 31, zp = (iz + 1) & 31;
#define IDX4V(X, Y, Z) ((((((X) * 32 + (Y)) * 32 + (Z)) << 4) >> 2) + ibq)
    const float4* nn4 = reinterpret_cast<const float4*>(g_nn);
    float4 a0 = nn4[IDX4V(xm, iy, zm)];
    float4 a1 = nn4[IDX4V(xm, iy, zp)];
    float4 a2 = nn4[IDX4V(xp, iy, zm)];
    float4 a3 = nn4[IDX4V(xp, iy, zp)];
    float4 a4 = nn4[IDX4V(ix, ym, zm)];
    float4 a5 = nn4[IDX4V(ix, ym, zp)];
    float4 a6 = nn4[IDX4V(ix, yp, zm)];
    float4 a7 = nn4[IDX4V(ix, yp, zp)];
#undef IDX4V
    const float4 os = reinterpret_cast<const float4*>(g_os)[t];
    float4 r;
    r.x = os.x + (a0.x + a1.x + a2.x + a3.x + a4.x + a5.x + a6.x + a7.x) * 0.125f;
    r.y = os.y + (a0.y + a1.y + a2.y + a3.y + a4.y + a5.y + a6.y + a7.y) * 0.125f;
    r.z = os.z + (a0.z + a1.z + a2.z + a3.z + a4.z + a5.z + a6.z + a7.z) * 0.125f;
    r.w = os.w + (a0.w + a1.w + a2.w + a3.w + a4.w + a5.w + a6.w + a7.w) * 0.125f;
    reinterpret_cast<float4*>(out)[t] = r;
    const float sg = expf(sigma_l[0]);
    reinterpret_cast<float4*>(out + NSAMP)[t] = make_float4(sg, sg, sg, sg);
}

extern "C" void kernel_launch(void* const* d_in, const int* in_sizes, int n_in,
                              void* d_out, int out_size)
{
    const float* x        = (const float*)d_in[0];
    const float* weight   = (const float*)d_in[1];
    const float* ag       = (const float*)d_in[2];
    const float* W1       = (const float*)d_in[3];
    const float* b1       = (const float*)d_in[4];
    const float* W2       = (const float*)d_in[5];
    const float* b2       = (const float*)d_in[6];
    const float* W3       = (const float*)d_in[7];
    const float* b3       = (const float*)d_in[8];
    const float* W1n      = (const float*)d_in[9];
    const float* b1n      = (const float*)d_in[10];
    const float* W2n      = (const float*)d_in[11];
    const float* b2n      = (const float*)d_in[12];
    const float* W3n      = (const float*)d_in[13];
    const float* b3n      = (const float*)d_in[14];
    const float* max_os_l = (const float*)d_in[15];
    const float* sigma_l  = (const float*)d_in[16];
    float* out = (float*)d_out;

    cudaFuncSetAttribute(mlp_kernel<true>,
                         cudaFuncAttributeMaxDynamicSharedMemorySize, SMEM_BYTES);
    cudaFuncSetAttribute(mlp_kernel<false>,
                         cudaFuncAttributeMaxDynamicSharedMemorySize, SMEM_BYTES);

    float* os_ptr = nullptr;
    float* nn_ptr = nullptr;
    cudaGetSymbolAddress((void**)&os_ptr, g_os);
    cudaGetSymbolAddress((void**)&nn_ptr, g_nn);

    mlp_kernel<true><<<GRID_MLP, TPB, SMEM_BYTES>>>(
        x, weight, W1, b1, W2, b2, W3, b3, ag, max_os_l, os_ptr);
    mlp_kernel<false><<<GRID_MLP, TPB, SMEM_BYTES>>>(
        x, weight, W1n, b1n, W2n, b2n, W3n, b3n, nullptr, max_os_l, nn_ptr);
    stencil_kernel<<<(NSAMP / 4 + 255) / 256, 256>>>(sigma_l, out);
}

// round 14
// speedup vs baseline: 1.4984x; 1.4984x over previous
#include <cuda_runtime.h>
#include <math.h>

// Problem dims
#define NXD 32
#define NYD 32
#define NZD 32
#define NBD 16
#define LMEMD 64
#define MIDD 128
#define NSAMP (NXD*NYD*NZD*NBD)   // 524288

// Tiling: thread tile = 4 hidden units x 8 samples; group = 32 samples.
#define TPB 128
#define SGRP 32
#define GRPS 8
#define SAMP_PER_BLOCK (SGRP * GRPS)     // 256
#define GRID_MLP (NSAMP / SAMP_PER_BLOCK) // 2048

// Shared layout (float offsets)
#define OFF_W1T   0          // [l][m] 64*128  = 8192
#define OFF_W2T   8192       // [k][n] 128*128 = 16384
#define OFF_HX    24576      // UNION: sXw[64][32]=2048 fl | sH[128][32]=4096 fl
#define OFF_ARP   28672      // [s][c] 32*4 = 128
#define OFF_W3    28800      // 128
#define SMEM_FLOATS 28928
#define SMEM_BYTES (SMEM_FLOATS * 4)     // 115,712 B -> 2 blocks/SM

typedef unsigned long long ull;

// Scratch (allocation-free rule: device globals)
__device__ float g_os[NSAMP];
__device__ float g_nn[NSAMP];

__device__ __forceinline__ ull pack2(float lo, float hi) {
    ull r;
    asm("mov.b64 %0, {%1, %2};" : "=l"(r) : "f"(lo), "f"(hi));
    return r;
}
__device__ __forceinline__ void unpack2(ull v, float& lo, float& hi) {
    asm("mov.b64 {%0, %1}, %2;" : "=f"(lo), "=f"(hi) : "l"(v));
}
// d = a * b + d  (packed 2x fp32, sm_100+)
__device__ __forceinline__ void fma2(ull& d, ull a, ull b) {
    asm("fma.rn.f32x2 %0, %1, %2, %3;" : "=l"(d) : "l"(a), "l"(b), "l"(d));
}
// Accurate fast tanh: tanh(x) = 1 - 2/(e^{2x}+1), via MUFU ex2 + rcp. ~1e-7 err.
__device__ __forceinline__ float tanh_fast(float x) {
    float e, r;
    const float t = x * 2.885390082f;           // 2 * log2(e)
    asm("ex2.approx.f32 %0, %1;" : "=f"(e) : "f"(t));
    asm("rcp.approx.f32 %0, %1;" : "=f"(r) : "f"(e + 1.0f));
    return fmaf(-2.0f, r, 1.0f);
}

template <bool WITH_AR>
__global__ __launch_bounds__(TPB)
void mlp_kernel(const float* __restrict__ x,
                const float* __restrict__ weight,
                const float* __restrict__ W1, const float* __restrict__ b1,
                const float* __restrict__ W2, const float* __restrict__ b2,
                const float* __restrict__ W3, const float* __restrict__ b3,
                const float* __restrict__ ag,
                const float* __restrict__ max_os_l,
                float* __restrict__ out)
{
    extern __shared__ float smem[];
    float* sW1T = smem + OFF_W1T;   // [l][m]  l<64,  m<128 (m contiguous)
    float* sW2T = smem + OFF_W2T;   // [k][n]  k<128, n<128 (n contiguous)
    float* sHX  = smem + OFF_HX;    // union: sXw [l][s] then sH [m][s]
    float* sArp = smem + OFF_ARP;   // [s][c]  s<32, c<4
    float* sW3  = smem + OFF_W3;    // [m]

    const int tid  = threadIdx.x;
    const int m0   = (tid >> 2) << 2;   // 4 hidden units per thread
    const int sb   = (tid & 3) << 3;    // 8 samples per thread
    const int s_ld = tid & 31;          // loader: sample
    const int c_ld = tid >> 5;          // loader: 16-float chunk (0..3)
    const int lane = tid & 31;
    const int wrp  = tid >> 5;          // warp id (0..3)

    float bb1[4], bb2[4];
    *reinterpret_cast<float4*>(bb1) = *reinterpret_cast<const float4*>(b1 + m0);
    *reinterpret_cast<float4*>(bb2) = *reinterpret_cast<const float4*>(b2 + m0);
    const float bb3 = b3[0];
    const float max_os = expf(max_os_l[0]);

    float wreg[16], agreg[16];
#pragma unroll
    for (int k = 0; k < 16; ++k) {
        wreg[k] = weight[c_ld * 16 + k];
        agreg[k] = WITH_AR ? ag[c_ld * 16 + k] : 0.0f;
    }

    // Stage transposed weights
    for (int i = tid; i < LMEMD * MIDD; i += TPB)
        sW1T[i] = W1[(i & 127) * LMEMD + (i >> 7)];
    for (int i = tid; i < MIDD * MIDD; i += TPB)
        sW2T[i] = W2[(i & 127) * MIDD + (i >> 7)];
    sW3[tid] = W3[tid];
    __syncthreads();

    const int base = blockIdx.x * SAMP_PER_BLOCK;
    const float* xbase = x + (size_t)(base + s_ld) * LMEMD + c_ld * 16;

    // Prefetch group 0 (each thread: 64B contiguous chunk, coalesced)
    float4 pv0, pv1, pv2, pv3;
    {
        const float4* xp = reinterpret_cast<const float4*>(xbase);
        pv0 = xp[0]; pv1 = xp[1]; pv2 = xp[2]; pv3 = xp[3];
    }

    for (int g = 0; g < GRPS; ++g) {
        // ---- A: build x_w in sXw (union low 8KB) + AR partials ----
        // STS bank = s_ld -> 32 distinct banks, conflict-free.
        {
            float xv[16];
            *reinterpret_cast<float4*>(&xv[0])  = pv0;
            *reinterpret_cast<float4*>(&xv[4])  = pv1;
            *reinterpret_cast<float4*>(&xv[8])  = pv2;
            *reinterpret_cast<float4*>(&xv[12]) = pv3;
            float arl = 0.0f;
#pragma unroll
            for (int k = 0; k < 16; ++k) {
                sHX[(c_ld * 16 + k) * SGRP + s_ld] = xv[k] * wreg[k];
                if (WITH_AR) arl = fmaf(xv[k], agreg[k], arl);
            }
            if (WITH_AR) sArp[s_ld * 4 + c_ld] = arl;
        }
        if (g + 1 < GRPS) {   // prefetch next group; consumed after ~6k cyc
            const float4* xp = reinterpret_cast<const float4*>(
                xbase + (size_t)(g + 1) * SGRP * LMEMD);
            pv0 = xp[0]; pv1 = xp[1]; pv2 = xp[2]; pv3 = xp[3];
        }
        __syncthreads();   // S1: sXw ready

        // ---- B: layer 1 (64 -> 128): 4m x 8s register tile ----
        ull acc[16];
#pragma unroll
        for (int mi = 0; mi < 4; ++mi) {
            const ull b = pack2(bb1[mi], bb1[mi]);
            acc[mi*4+0] = b; acc[mi*4+1] = b; acc[mi*4+2] = b; acc[mi*4+3] = b;
        }
#pragma unroll 4
        for (int l = 0; l < LMEMD; ++l) {
            float wq[4];
            *reinterpret_cast<float4*>(wq) =
                *reinterpret_cast<const float4*>(&sW1T[(l << 7) + m0]);
            const ulonglong2 xq0 =
                *reinterpret_cast<const ulonglong2*>(&sHX[l * SGRP + sb]);
            const ulonglong2 xq1 =
                *reinterpret_cast<const ulonglong2*>(&sHX[l * SGRP + sb + 4]);
#pragma unroll
            for (int mi = 0; mi < 4; ++mi) {
                const ull w2 = pack2(wq[mi], wq[mi]);
                fma2(acc[mi*4+0], w2, xq0.x);
                fma2(acc[mi*4+1], w2, xq0.y);
                fma2(acc[mi*4+2], w2, xq1.x);
                fma2(acc[mi*4+3], w2, xq1.y);
            }
        }
        __syncthreads();   // S1b: all sXw reads done (sH will overwrite union)

        // ---- B2: tanh -> sH[m][s] ----
#pragma unroll
        for (int mi = 0; mi < 4; ++mi) {
            float l0, h0, l1, h1, l2, h2, l3, h3;
            unpack2(acc[mi*4+0], l0, h0);
            unpack2(acc[mi*4+1], l1, h1);
            unpack2(acc[mi*4+2], l2, h2);
            unpack2(acc[mi*4+3], l3, h3);
            float4 t0 = make_float4(tanh_fast(l0), tanh_fast(h0),
                                    tanh_fast(l1), tanh_fast(h1));
            float4 t1 = make_float4(tanh_fast(l2), tanh_fast(h2),
                                    tanh_fast(l3), tanh_fast(h3));
            *reinterpret_cast<float4*>(&sHX[(m0 + mi) * SGRP + sb])     = t0;
            *reinterpret_cast<float4*>(&sHX[(m0 + mi) * SGRP + sb + 4]) = t1;
        }
        __syncthreads();   // S2: h1 ready

        // ---- C: layer 2 (128 -> 128) ----
#pragma unroll
        for (int mi = 0; mi < 4; ++mi) {
            const ull b = pack2(bb2[mi], bb2[mi]);
            acc[mi*4+0] = b; acc[mi*4+1] = b; acc[mi*4+2] = b; acc[mi*4+3] = b;
        }
#pragma unroll 4
        for (int k = 0; k < MIDD; ++k) {
            float wq[4];
            *reinterpret_cast<float4*>(wq) =
                *reinterpret_cast<const float4*>(&sW2T[(k << 7) + m0]);
            const ulonglong2 hq0 =
                *reinterpret_cast<const ulonglong2*>(&sHX[k * SGRP + sb]);
            const ulonglong2 hq1 =
                *reinterpret_cast<const ulonglong2*>(&sHX[k * SGRP + sb + 4]);
#pragma unroll
            for (int mi = 0; mi < 4; ++mi) {
                const ull w2 = pack2(wq[mi], wq[mi]);
                fma2(acc[mi*4+0], w2, hq0.x);
                fma2(acc[mi*4+1], w2, hq0.y);
                fma2(acc[mi*4+2], w2, hq1.x);
                fma2(acc[mi*4+3], w2, hq1.y);
            }
        }
        __syncthreads();   // S3: all layer-2 reads of sH done

        // ---- D: tanh(h2) -> sH in place ----
#pragma unroll
        for (int mi = 0; mi < 4; ++mi) {
            float l0, h0, l1, h1, l2, h2, l3, h3;
            unpack2(acc[mi*4+0], l0, h0);
            unpack2(acc[mi*4+1], l1, h1);
            unpack2(acc[mi*4+2], l2, h2);
            unpack2(acc[mi*4+3], l3, h3);
            float4 t0 = make_float4(tanh_fast(l0), tanh_fast(h0),
                                    tanh_fast(l1), tanh_fast(h1));
            float4 t1 = make_float4(tanh_fast(l2), tanh_fast(h2),
                                    tanh_fast(l3), tanh_fast(h3));
            *reinterpret_cast<float4*>(&sHX[(m0 + mi) * SGRP + sb])     = t0;
            *reinterpret_cast<float4*>(&sHX[(m0 + mi) * SGRP + sb + 4]) = t1;
        }
        __syncthreads();   // S4: h2 ready

        // ---- E: layer 3 reduce + AR (all 4 warps; warp w -> samples 8w..8w+7)
        // Each warp: 4 lanes per sample (lane>>3 = quarter), 32 m's each,
        // then a 2-step shuffle reduce within the 4-lane team.
        {
            const int sE = (wrp << 3) + (lane & 7);   // sample handled
            const int q  = lane >> 3;                 // quarter 0..3
            float a = 0.0f;
#pragma unroll 8
            for (int mm = q * 32; mm < q * 32 + 32; mm += 4) {
                a = fmaf(sW3[mm + 0], sHX[(mm + 0) * SGRP + sE], a);
                a = fmaf(sW3[mm + 1], sHX[(mm + 1) * SGRP + sE], a);
                a = fmaf(sW3[mm + 2], sHX[(mm + 2) * SGRP + sE], a);
                a = fmaf(sW3[mm + 3], sHX[(mm + 3) * SGRP + sE], a);
            }
            a += __shfl_xor_sync(0xffffffffu, a, 16);
            a += __shfl_xor_sync(0xffffffffu, a, 8);
            if (q == 0) {
                float val = tanh_fast(a + bb3) * max_os;
                if (WITH_AR) {
                    val += (sArp[sE * 4 + 0] + sArp[sE * 4 + 1])
                         + (sArp[sE * 4 + 2] + sArp[sE * 4 + 3]);
                }
                out[base + g * SGRP + sE] = val;
            }
        }
        __syncthreads();   // S5: protect union before next group's A
    }
}

// 8-point periodic stencil on g_nn + combine + sigma (float4-vectorized).
__global__ void stencil_kernel(const float* __restrict__ sigma_l,
                               float* __restrict__ out)
{
    const int t = blockIdx.x * blockDim.x + threadIdx.x;   // 0 .. NSAMP/4-1
    if (t >= NSAMP / 4) return;
    const int idx = t * 4;
    const int ibq = (idx & 15) >> 2;
    const int iz = (idx >> 4) & 31;
    const int iy = (idx >> 9) & 31;
    const int ix = (idx >> 14) & 31;
    const int xm = (ix + 31) & 31, xp = (ix + 1) & 31;
    const int ym = (iy + 31) & 31, yp = (iy + 1) & 31;
    const int zm = (iz + 31) & 31, zp = (iz + 1) & 31;
#define IDX4V(X, Y, Z) ((((((X) * 32 + (Y)) * 32 + (Z)) << 4) >> 2) + ibq)
    const float4* nn4 = reinterpret_cast<const float4*>(g_nn);
    float4 a0 = nn4[IDX4V(xm, iy, zm)];
    float4 a1 = nn4[IDX4V(xm, iy, zp)];
    float4 a2 = nn4[IDX4V(xp, iy, zm)];
    float4 a3 = nn4[IDX4V(xp, iy, zp)];
    float4 a4 = nn4[IDX4V(ix, ym, zm)];
    float4 a5 = nn4[IDX4V(ix, ym, zp)];
    float4 a6 = nn4[IDX4V(ix, yp, zm)];
    float4 a7 = nn4[IDX4V(ix, yp, zp)];
#undef IDX4V
    const float4 os = reinterpret_cast<const float4*>(g_os)[t];
    float4 r;
    r.x = os.x + (a0.x + a1.x + a2.x + a3.x + a4.x + a5.x + a6.x + a7.x) * 0.125f;
    r.y = os.y + (a0.y + a1.y + a2.y + a3.y + a4.y + a5.y + a6.y + a7.y) * 0.125f;
    r.z = os.z + (a0.z + a1.z + a2.z + a3.z + a4.z + a5.z + a6.z + a7.z) * 0.125f;
    r.w = os.w + (a0.w + a1.w + a2.w + a3.w + a4.w + a5.w + a6.w + a7.w) * 0.125f;
    reinterpret_cast<float4*>(out)[t] = r;
    const float sg = expf(sigma_l[0]);
    reinterpret_cast<float4*>(out + NSAMP)[t] = make_float4(sg, sg, sg, sg);
}

extern "C" void kernel_launch(void* const* d_in, const int* in_sizes, int n_in,
                              void* d_out, int out_size)
{
    const float* x        = (const float*)d_in[0];
    const float* weight   = (const float*)d_in[1];
    const float* ag       = (const float*)d_in[2];
    const float* W1       = (const float*)d_in[3];
    const float* b1       = (const float*)d_in[4];
    const float* W2       = (const float*)d_in[5];
    const float* b2       = (const float*)d_in[6];
    const float* W3       = (const float*)d_in[7];
    const float* b3       = (const float*)d_in[8];
    const float* W1n      = (const float*)d_in[9];
    const float* b1n      = (const float*)d_in[10];
    const float* W2n      = (const float*)d_in[11];
    const float* b2n      = (const float*)d_in[12];
    const float* W3n      = (const float*)d_in[13];
    const float* b3n      = (const float*)d_in[14];
    const float* max_os_l = (const float*)d_in[15];
    const float* sigma_l  = (const float*)d_in[16];
    float* out = (float*)d_out;

    cudaFuncSetAttribute(mlp_kernel<true>,
                         cudaFuncAttributeMaxDynamicSharedMemorySize, SMEM_BYTES);
    cudaFuncSetAttribute(mlp_kernel<false>,
                         cudaFuncAttributeMaxDynamicSharedMemorySize, SMEM_BYTES);

    float* os_ptr = nullptr;
    float* nn_ptr = nullptr;
    cudaGetSymbolAddress((void**)&os_ptr, g_os);
    cudaGetSymbolAddress((void**)&nn_ptr, g_nn);

    mlp_kernel<true><<<GRID_MLP, TPB, SMEM_BYTES>>>(
        x, weight, W1, b1, W2, b2, W3, b3, ag, max_os_l, os_ptr);
    mlp_kernel<false><<<GRID_MLP, TPB, SMEM_BYTES>>>(
        x, weight, W1n, b1n, W2n, b2n, W3n, b3n, nullptr, max_os_l, nn_ptr);
    stencil_kernel<<<(NSAMP / 4 + 255) / 256, 256>>>(sigma_l, out);
}